// round 13
// baseline (speedup 1.0000x reference)
#include <cuda_runtime.h>
#include <cuda_bf16.h>
#include <math.h>
#include <stdint.h>

#define BSZ 256
#define D   512
#define KC  64
#define NKC 8
#define MT  128
#define NT  128
#define GROW 132
#define NEG (-1.0e30f)

// ---- mainloop smem: 3-stage ring, each stage = W(16KB) + Y(16KB) ----
#define STAGE_BYTES 32768
#define RING_OFF(st) ((st)*STAGE_BYTES)
#define YOFS 16384
#define G_OFF  0                 /* G[128][132] f32 = 67584, union with ring */
#define MP_OFF   98304
#define RS_OFF   98320
#define RED_OFF  98832
#define SMEM_BYTES 98976

#define SW(o) ((o) ^ ((((unsigned)(o))>>3)&0x70u))

// ---- device scratch ----
__device__ __nv_bfloat16 g_W[BSZ*BSZ*D];   // 64 MiB: W[s][a][d] = x[a,d]*z[s,d]
__device__ __nv_bfloat16 g_Yb[BSZ*D];
__device__ float g_px2_m[BSZ*BSZ*2];
__device__ float g_px2_s[BSZ*BSZ*2];
__device__ float g_py2_m[BSZ*BSZ*2];
__device__ float g_py2_s[BSZ*BSZ*2];
__device__ float g_pz_m[BSZ*4];
__device__ float g_pz_s[BSZ*4];
__device__ float g_line[BSZ];
__device__ int   g_ctr;

static __device__ __forceinline__ uint32_t smem_u32(const void* p){
    uint32_t a;
    asm("{ .reg .u64 t; cvta.to.shared.u64 t, %1; cvt.u32.u64 %0, t; }" : "=r"(a) : "l"(p));
    return a;
}
#define LDSM_X4(r0,r1,r2,r3, addr) \
    asm volatile("ldmatrix.sync.aligned.m8n8.x4.shared.b16 {%0,%1,%2,%3}, [%4];" \
        : "=r"(r0),"=r"(r1),"=r"(r2),"=r"(r3) : "r"(addr))

__device__ __forceinline__ void lse_merge(float& M, float& S, float m2, float s2){
    if (m2 > M){ S = S * __expf(M - m2) + s2; M = m2; }
    else       { S = S + s2 * __expf(m2 - M); }
}

// ============ prep v2: register-resident streaming, no smem ============
// blocks [0,512): W. bid = s*2 + ahalf. Thread (rg=tid>>6, tg=tid&63) pins
// z[s, tg*8..tg*8+8) in regs, streams 32 x-rows (a = ahalf*128 + i*4 + rg),
// one STG.128 per row. blocks [512,576): Y -> bf16.
__global__ void __launch_bounds__(256)
prep_kernel(const float* __restrict__ X, const float* __restrict__ Y,
            const float* __restrict__ Z){
    const int tid = threadIdx.x, bid = blockIdx.x;
    if (bid < 512){
        const int s = bid >> 1, ahalf = bid & 1;
        const int rg = tid >> 6, tg = tid & 63;
        const int d8 = tg * 8;
        const float4 z0 = *(const float4*)(Z + (size_t)s*D + d8);
        const float4 z1 = *(const float4*)(Z + (size_t)s*D + d8 + 4);
        const int aStart = ahalf*128 + rg;
        #pragma unroll 4
        for (int i = 0; i < 32; ++i){
            const int a = aStart + i*4;
            const float4 x0 = *(const float4*)(X + (size_t)a*D + d8);
            const float4 x1 = *(const float4*)(X + (size_t)a*D + d8 + 4);
            __nv_bfloat162 r0 = __floats2bfloat162_rn(x0.x*z0.x, x0.y*z0.y);
            __nv_bfloat162 r1 = __floats2bfloat162_rn(x0.z*z0.z, x0.w*z0.w);
            __nv_bfloat162 r2 = __floats2bfloat162_rn(x1.x*z1.x, x1.y*z1.y);
            __nv_bfloat162 r3 = __floats2bfloat162_rn(x1.z*z1.z, x1.w*z1.w);
            *(uint4*)(g_W + ((size_t)s*BSZ + a)*D + d8) =
                make_uint4(*(uint32_t*)&r0, *(uint32_t*)&r1,
                           *(uint32_t*)&r2, *(uint32_t*)&r3);
        }
    } else {
        int base = ((bid - 512)*256 + tid)*8;
        float4 v0 = *(const float4*)(Y + base);
        float4 v1 = *(const float4*)(Y + base + 4);
        __nv_bfloat162 r0 = __floats2bfloat162_rn(v0.x, v0.y);
        __nv_bfloat162 r1 = __floats2bfloat162_rn(v0.z, v0.w);
        __nv_bfloat162 r2 = __floats2bfloat162_rn(v1.x, v1.y);
        __nv_bfloat162 r3 = __floats2bfloat162_rn(v1.z, v1.w);
        *(uint4*)(g_Yb + base) = make_uint4(*(uint32_t*)&r0, *(uint32_t*)&r1,
                                            *(uint32_t*)&r2, *(uint32_t*)&r3);
    }
}

// ============ main: one 128x128 quadrant per CTA ============
static __device__ __forceinline__ void issue_chunk(uint32_t sb, int stage,
                                                   const __nv_bfloat16* wRow0,
                                                   const __nv_bfloat16* yRow0,
                                                   int k0, int tid){
    const uint32_t base = sb + RING_OFF(stage);
    #pragma unroll
    for (int i = 0; i < 4; ++i){
        int gi = tid + 256*i;
        int row = gi >> 3, u = gi & 7;
        uint32_t so = SW((uint32_t)(row*128 + u*16));
        asm volatile("cp.async.cg.shared.global [%0], [%1], 16;"
            :: "r"(base + so),
               "l"(__cvta_generic_to_global(wRow0 + (size_t)row*D + k0 + u*8)) : "memory");
        asm volatile("cp.async.cg.shared.global [%0], [%1], 16;"
            :: "r"(base + YOFS + so),
               "l"(__cvta_generic_to_global(yRow0 + (size_t)row*D + k0 + u*8)) : "memory");
    }
    asm volatile("cp.async.commit_group;" ::: "memory");
}

__global__ void __launch_bounds__(256, 2)
symile_quad(){
    extern __shared__ char smem[];
    const uint32_t sb = smem_u32(smem);
    const int tid = threadIdx.x, warp = tid >> 5, lane = tid & 31;
    const int s = blockIdx.x >> 2;
    const int half = (blockIdx.x >> 1) & 1, nh = blockIdx.x & 1;
    const int aBase = half * MT, rBase = nh * NT;
    const int wm = warp & 3, wn = warp >> 2;
    const int lrow = lane & 7, lsel = lane >> 3;
    const int g = lane >> 2, tg = lane & 3;

    const __nv_bfloat16* wRow0 = g_W + ((size_t)s*BSZ + aBase)*D;
    const __nv_bfloat16* yRow0 = g_Yb + (size_t)rBase*D;

    float* G     = (float*)(smem + G_OFF);
    float* rowS  = (float*)(smem + RS_OFF);
    float* red   = (float*)(smem + RED_OFF);
    float* mpp   = (float*)(smem + MP_OFF);

    float c[2][8][4];
    #pragma unroll
    for (int mt = 0; mt < 2; ++mt)
        #pragma unroll
        for (int nt = 0; nt < 8; ++nt)
            #pragma unroll
            for (int i = 0; i < 4; ++i) c[mt][nt][i] = 0.f;

    issue_chunk(sb, 0, wRow0, yRow0, 0, tid);
    issue_chunk(sb, 1, wRow0, yRow0, KC, tid);

    for (int kc = 0; kc < NKC; ++kc){
        // wait for stage kc, then ONE barrier, then refill (kc+2)%3 == (kc-1)%3
        if (kc < NKC-1) asm volatile("cp.async.wait_group 1;" ::: "memory");
        else            asm volatile("cp.async.wait_group 0;" ::: "memory");
        __syncthreads();
        if (kc + 2 < NKC)
            issue_chunk(sb, (kc+2)%3, wRow0, yRow0, (kc+2)*KC, tid);

        const uint32_t sA = sb + RING_OFF(kc%3);
        const uint32_t sB = sA + YOFS;
        #pragma unroll
        for (int ks = 0; ks < 4; ++ks){
            unsigned a[2][4], bb[8][2];
            {
                uint32_t arow = (uint32_t)(wm*32 + (lsel & 1)*8 + lrow);
                uint32_t acol = (uint32_t)(ks*32 + (lsel >> 1)*16);
                #pragma unroll
                for (int mt = 0; mt < 2; ++mt){
                    uint32_t o = (arow + mt*16)*128 + acol;
                    LDSM_X4(a[mt][0], a[mt][1], a[mt][2], a[mt][3], sA + SW(o));
                }
            }
            {
                uint32_t brow = (uint32_t)(wn*64 + (lsel >> 1)*8 + lrow);
                uint32_t bcol = (uint32_t)(ks*32 + (lsel & 1)*16);
                #pragma unroll
                for (int p = 0; p < 4; ++p){
                    uint32_t o = (brow + p*16)*128 + bcol;
                    LDSM_X4(bb[2*p][0], bb[2*p][1], bb[2*p+1][0], bb[2*p+1][1], sB + SW(o));
                }
            }
            #pragma unroll
            for (int mt = 0; mt < 2; ++mt)
                #pragma unroll
                for (int nt = 0; nt < 8; ++nt)
                    asm volatile(
                      "mma.sync.aligned.m16n8k16.row.col.f32.bf16.bf16.f32 "
                      "{%0,%1,%2,%3}, {%4,%5,%6,%7}, {%8,%9}, {%0,%1,%2,%3};\n"
                      : "+f"(c[mt][nt][0]), "+f"(c[mt][nt][1]),
                        "+f"(c[mt][nt][2]), "+f"(c[mt][nt][3])
                      : "r"(a[mt][0]), "r"(a[mt][1]), "r"(a[mt][2]), "r"(a[mt][3]),
                        "r"(bb[nt][0]), "r"(bb[nt][1]));
        }
    }

    // ---- plane max from accumulator registers ----
    {
        float m = NEG;
        #pragma unroll
        for (int mt = 0; mt < 2; ++mt)
            #pragma unroll
            for (int nt = 0; nt < 8; ++nt){
                float m01 = fmaxf(c[mt][nt][0], c[mt][nt][1]);
                float m23 = fmaxf(c[mt][nt][2], c[mt][nt][3]);
                m = fmaxf(m, fmaxf(m01, m23));
            }
        #pragma unroll
        for (int off = 16; off > 0; off >>= 1)
            m = fmaxf(m, __shfl_xor_sync(0xffffffffu, m, off));
        if (lane == 0) red[warp] = m;
    }
    __syncthreads();      // also fences last mma reads before G spill reuses ring
    if (tid == 0){
        float m = red[0];
        #pragma unroll
        for (int w = 1; w < 8; ++w) m = fmaxf(m, red[w]);
        mpp[0] = m;
    }
    __syncthreads();
    const float mp = mpp[0];

    // ---- spill exp(c - mp) into G ----
    #pragma unroll
    for (int mt = 0; mt < 2; ++mt)
        #pragma unroll
        for (int nt = 0; nt < 8; ++nt){
            int row = wm*32 + mt*16 + g;
            int col = wn*64 + nt*8 + tg*2;
            *(float2*)&G[row*GROW + col] =
                make_float2(__expf(c[mt][nt][0]-mp), __expf(c[mt][nt][1]-mp));
            *(float2*)&G[(row+8)*GROW + col] =
                make_float2(__expf(c[mt][nt][2]-mp), __expf(c[mt][nt][3]-mp));
        }
    __syncthreads();

    const int row = tid >> 1, part = tid & 1;

    // ---- row sums ----
    {
        const float* Gr = G + row*GROW + part*64;
        float sum = 0.f;
        #pragma unroll
        for (int q = 0; q < 16; ++q){
            float4 v = *(const float4*)(Gr + q*4);
            sum += (v.x + v.y) + (v.z + v.w);
        }
        sum += __shfl_xor_sync(0xffffffffu, sum, 1);
        if (part == 0){
            rowS[row] = sum;
            int idx = (s*BSZ + aBase + row)*2 + nh;
            g_px2_m[idx] = mp; g_px2_s[idx] = sum;
        }
    }
    __syncthreads();

    // ---- col sums + plane sum ----
    {
        const int col = tid >> 1;
        const float* Gc = G + part*64*GROW + col;
        float sum = 0.f;
        #pragma unroll 8
        for (int rr = 0; rr < 64; ++rr) sum += Gc[rr*GROW];
        sum += __shfl_xor_sync(0xffffffffu, sum, 1);
        if (part == 0){
            int idx = (s*BSZ + rBase + col)*2 + half;
            g_py2_m[idx] = mp; g_py2_s[idx] = sum;
        }
    }
    if (warp < 4){
        float v = rowS[warp*32 + lane];
        #pragma unroll
        for (int off = 16; off > 0; off >>= 1)
            v += __shfl_xor_sync(0xffffffffu, v, off);
        if (lane == 0) red[8 + warp] = v;
    }
    __syncthreads();
    if (tid == 0){
        int idx = s*4 + half*2 + nh;
        g_pz_m[idx] = mp;
        g_pz_s[idx] = (red[8] + red[9]) + (red[10] + red[11]);
    }
}

// ============ finalize: per-line losses + last-block global sum ============
__global__ void finalize(const float* __restrict__ X, const float* __restrict__ Y,
                         const float* __restrict__ Z, float* __restrict__ out){
    __shared__ float wred[8*5];
    __shared__ int lastFlag;
    const int t = blockIdx.x, si = threadIdx.x;
    const int warp = si >> 5, lane = si & 31;

    float Mx = NEG, Sx = 0.f, My = NEG, Sy = 0.f;
    {
        int b = (si*BSZ + t)*2;
        lse_merge(Mx, Sx, g_px2_m[b],   g_px2_s[b]);
        lse_merge(Mx, Sx, g_px2_m[b+1], g_px2_s[b+1]);
        lse_merge(My, Sy, g_py2_m[b],   g_py2_s[b]);
        lse_merge(My, Sy, g_py2_m[b+1], g_py2_s[b+1]);
    }
    float dg = X[t*D + 2*si]   * Y[t*D + 2*si]   * Z[t*D + 2*si]
             + X[t*D + 2*si+1] * Y[t*D + 2*si+1] * Z[t*D + 2*si+1];

    #pragma unroll
    for (int off = 16; off > 0; off >>= 1){
        float m2 = __shfl_xor_sync(0xffffffffu, Mx, off);
        float s2 = __shfl_xor_sync(0xffffffffu, Sx, off);
        lse_merge(Mx, Sx, m2, s2);
        m2 = __shfl_xor_sync(0xffffffffu, My, off);
        s2 = __shfl_xor_sync(0xffffffffu, Sy, off);
        lse_merge(My, Sy, m2, s2);
        dg += __shfl_xor_sync(0xffffffffu, dg, off);
    }
    if (lane == 0){
        wred[warp*5+0] = Mx; wred[warp*5+1] = Sx;
        wred[warp*5+2] = My; wred[warp*5+3] = Sy;
        wred[warp*5+4] = dg;
    }
    __syncthreads();
    if (si == 0){
        float MX = NEG, SX = 0.f, MY = NEG, SY = 0.f, DG = 0.f;
        #pragma unroll
        for (int w = 0; w < 8; ++w){
            lse_merge(MX, SX, wred[w*5+0], wred[w*5+1]);
            lse_merge(MY, SY, wred[w*5+2], wred[w*5+3]);
            DG += wred[w*5+4];
        }
        float MZ = NEG, SZ = 0.f;
        #pragma unroll
        for (int q = 0; q < 4; ++q)
            lse_merge(MZ, SZ, g_pz_m[t*4+q], g_pz_s[t*4+q]);
        g_line[t] = (MX + logf(SX)) + (MY + logf(SY)) + (MZ + logf(SZ)) - 3.f*DG;
        __threadfence();
        lastFlag = (atomicAdd(&g_ctr, 1) == BSZ - 1) ? 1 : 0;
    }
    __syncthreads();
    if (lastFlag){
        if (warp == 0){
            float v = 0.f;
            #pragma unroll
            for (int j = 0; j < 8; ++j) v += g_line[lane + j*32];
            #pragma unroll
            for (int off = 16; off > 0; off >>= 1)
                v += __shfl_xor_sync(0xffffffffu, v, off);
            if (lane == 0){
                out[0] = v / 768.f;
                g_ctr = 0;
            }
        }
    }
}

extern "C" void kernel_launch(void* const* d_in, const int* in_sizes, int n_in,
                              void* d_out, int out_size){
    const float* X = (const float*)d_in[0];
    const float* Y = (const float*)d_in[1];
    const float* Z = (const float*)d_in[2];
    float* out = (float*)d_out;

    cudaFuncSetAttribute(symile_quad, cudaFuncAttributeMaxDynamicSharedMemorySize, SMEM_BYTES);

    prep_kernel<<<576, 256>>>(X, Y, Z);
    symile_quad<<<BSZ*4, 256, SMEM_BYTES>>>();
    finalize<<<BSZ, 256>>>(X, Y, Z, out);
}

// round 17
// speedup vs baseline: 1.0519x; 1.0519x over previous
#include <cuda_runtime.h>
#include <cuda_bf16.h>
#include <math.h>
#include <stdint.h>

#define BSZ 256
#define D   512
#define KC  64
#define NKC 8
#define MT  128
#define NT  128
#define GROW 132
#define NEG (-1.0e30f)

// ---- smem: 3-stage ring (A=X->W in place 16KB + Y 16KB per stage) ----
#define STAGE_BYTES 32768
#define RING_OFF(st) ((st)*STAGE_BYTES)
#define YOFS 16384
#define G_OFF   0                /* G[128][132] f32 = 67584, union with ring */
#define ZBUF_OFF 98304           /* 1 KB: z[s][0..512) bf16 */
#define MP_OFF   99328
#define RS_OFF   99344
#define RED_OFF  99856
#define SMEM_BYTES 99968

#define SW(o) ((o) ^ ((((unsigned)(o))>>3)&0x70u))

// ---- device scratch ----
__device__ __nv_bfloat16 g_Xb[BSZ*D];
__device__ __nv_bfloat16 g_Yb[BSZ*D];
__device__ __nv_bfloat16 g_Zb[BSZ*D];
__device__ float g_px2_m[BSZ*BSZ*2];
__device__ float g_px2_s[BSZ*BSZ*2];
__device__ float g_py2_m[BSZ*BSZ*2];
__device__ float g_py2_s[BSZ*BSZ*2];
__device__ float g_pz_m[BSZ*4];
__device__ float g_pz_s[BSZ*4];
__device__ float g_line[BSZ];
__device__ int   g_ctr;

static __device__ __forceinline__ uint32_t smem_u32(const void* p){
    uint32_t a;
    asm("{ .reg .u64 t; cvta.to.shared.u64 t, %1; cvt.u32.u64 %0, t; }" : "=r"(a) : "l"(p));
    return a;
}
#define LDSM_X4(r0,r1,r2,r3, addr) \
    asm volatile("ldmatrix.sync.aligned.m8n8.x4.shared.b16 {%0,%1,%2,%3}, [%4];" \
        : "=r"(r0),"=r"(r1),"=r"(r2),"=r"(r3) : "r"(addr))

__device__ __forceinline__ void lse_merge(float& M, float& S, float m2, float s2){
    if (m2 > M){ S = S * __expf(M - m2) + s2; M = m2; }
    else       { S = S + s2 * __expf(m2 - M); }
}

// ============ conv: X,Y,Z -> bf16 (tiny) ============
__global__ void conv_kernel(const float* __restrict__ X, const float* __restrict__ Y,
                            const float* __restrict__ Z){
    const int tid = threadIdx.x, bid = blockIdx.x;
    const int sec = bid >> 6;                        // 0:X 1:Y 2:Z
    const float* src = (sec == 0) ? X : (sec == 1) ? Y : Z;
    __nv_bfloat16* dst = (sec == 0) ? g_Xb : (sec == 1) ? g_Yb : g_Zb;
    int base = ((bid & 63)*256 + tid)*8;
    float4 v0 = *(const float4*)(src + base);
    float4 v1 = *(const float4*)(src + base + 4);
    __nv_bfloat162 r0 = __floats2bfloat162_rn(v0.x, v0.y);
    __nv_bfloat162 r1 = __floats2bfloat162_rn(v0.z, v0.w);
    __nv_bfloat162 r2 = __floats2bfloat162_rn(v1.x, v1.y);
    __nv_bfloat162 r3 = __floats2bfloat162_rn(v1.z, v1.w);
    *(uint4*)(dst + base) = make_uint4(*(uint32_t*)&r0, *(uint32_t*)&r1,
                                       *(uint32_t*)&r2, *(uint32_t*)&r3);
}

// ============ main: one 128x128 quadrant per CTA ============
static __device__ __forceinline__ void issue_chunk(uint32_t sb, int stage,
                                                   const __nv_bfloat16* xRow0,
                                                   const __nv_bfloat16* yRow0,
                                                   int k0, int tid){
    const uint32_t base = sb + RING_OFF(stage);
    #pragma unroll
    for (int i = 0; i < 4; ++i){
        int gi = tid + 256*i;
        int row = gi >> 3, u = gi & 7;
        uint32_t so = SW((uint32_t)(row*128 + u*16));
        asm volatile("cp.async.cg.shared.global [%0], [%1], 16;"
            :: "r"(base + so),
               "l"(__cvta_generic_to_global(xRow0 + (size_t)row*D + k0 + u*8)) : "memory");
        asm volatile("cp.async.cg.shared.global [%0], [%1], 16;"
            :: "r"(base + YOFS + so),
               "l"(__cvta_generic_to_global(yRow0 + (size_t)row*D + k0 + u*8)) : "memory");
    }
    asm volatile("cp.async.commit_group;" ::: "memory");
}

// in-place X -> W = X .* z on stage's A buffer (thread-local RMW, smem only)
static __device__ __forceinline__ void convert_stage(uint32_t sb, int stage,
                                                     uint32_t zchunk, int tid){
    const uint32_t base = sb + RING_OFF(stage);
    #pragma unroll
    for (int i = 0; i < 4; ++i){
        int gi = tid + 256*i;
        int row = gi >> 3, u = gi & 7;
        uint32_t addr = base + SW((uint32_t)(row*128 + u*16));
        uint32_t x0,x1,x2,x3, z0,z1,z2,z3;
        asm volatile("ld.shared.v4.b32 {%0,%1,%2,%3}, [%4];"
            : "=r"(x0),"=r"(x1),"=r"(x2),"=r"(x3) : "r"(addr));
        asm volatile("ld.shared.v4.b32 {%0,%1,%2,%3}, [%4];"
            : "=r"(z0),"=r"(z1),"=r"(z2),"=r"(z3) : "r"(zchunk + (uint32_t)(u*16)));
        __nv_bfloat162 p0 = __hmul2(*(__nv_bfloat162*)&x0, *(__nv_bfloat162*)&z0);
        __nv_bfloat162 p1 = __hmul2(*(__nv_bfloat162*)&x1, *(__nv_bfloat162*)&z1);
        __nv_bfloat162 p2 = __hmul2(*(__nv_bfloat162*)&x2, *(__nv_bfloat162*)&z2);
        __nv_bfloat162 p3 = __hmul2(*(__nv_bfloat162*)&x3, *(__nv_bfloat162*)&z3);
        asm volatile("st.shared.v4.b32 [%0], {%1,%2,%3,%4};"
            :: "r"(addr), "r"(*(uint32_t*)&p0), "r"(*(uint32_t*)&p1),
               "r"(*(uint32_t*)&p2), "r"(*(uint32_t*)&p3) : "memory");
    }
}

__global__ void __launch_bounds__(256, 2)
symile_quad(){
    extern __shared__ char smem[];
    const uint32_t sb = smem_u32(smem);
    const int tid = threadIdx.x, warp = tid >> 5, lane = tid & 31;
    const int s = blockIdx.x >> 2;
    const int half = (blockIdx.x >> 1) & 1, nh = blockIdx.x & 1;
    const int aBase = half * MT, rBase = nh * NT;
    const int wm = warp & 3, wn = warp >> 2;
    const int lrow = lane & 7, lsel = lane >> 3;
    const int g = lane >> 2, tg = lane & 3;

    const __nv_bfloat16* xRow0 = g_Xb + (size_t)aBase*D;
    const __nv_bfloat16* yRow0 = g_Yb + (size_t)rBase*D;

    float* G     = (float*)(smem + G_OFF);
    float* rowS  = (float*)(smem + RS_OFF);
    float* red   = (float*)(smem + RED_OFF);
    float* mpp   = (float*)(smem + MP_OFF);
    const uint32_t zbuf = sb + ZBUF_OFF;

    float c[2][8][4];
    #pragma unroll
    for (int mt = 0; mt < 2; ++mt)
        #pragma unroll
        for (int nt = 0; nt < 8; ++nt)
            #pragma unroll
            for (int i = 0; i < 4; ++i) c[mt][nt][i] = 0.f;

    // zbuf: full z row (1 KB) via cp.async, grouped with chunk 0
    if (tid < 64){
        asm volatile("cp.async.cg.shared.global [%0], [%1], 16;"
            :: "r"(zbuf + (uint32_t)(tid*16)),
               "l"(__cvta_generic_to_global(g_Zb + (size_t)s*D + tid*8)) : "memory");
    }
    issue_chunk(sb, 0, xRow0, yRow0, 0, tid);     // commit includes zbuf
    issue_chunk(sb, 1, xRow0, yRow0, KC, tid);

    for (int kc = 0; kc < NKC; ++kc){
        if (kc < NKC-1) asm volatile("cp.async.wait_group 1;" ::: "memory");
        else            asm volatile("cp.async.wait_group 0;" ::: "memory");
        __syncthreads();
        if (kc + 2 < NKC)
            issue_chunk(sb, (kc+2)%3, xRow0, yRow0, (kc+2)*KC, tid);

        convert_stage(sb, kc%3, zbuf + (uint32_t)(kc*128), tid);
        __syncthreads();                           // W visible for ldmatrix

        const uint32_t sA = sb + RING_OFF(kc%3);
        const uint32_t sB = sA + YOFS;
        #pragma unroll
        for (int ks = 0; ks < 4; ++ks){
            unsigned a[2][4], bb[8][2];
            {
                uint32_t arow = (uint32_t)(wm*32 + (lsel & 1)*8 + lrow);
                uint32_t acol = (uint32_t)(ks*32 + (lsel >> 1)*16);
                #pragma unroll
                for (int mt = 0; mt < 2; ++mt){
                    uint32_t o = (arow + mt*16)*128 + acol;
                    LDSM_X4(a[mt][0], a[mt][1], a[mt][2], a[mt][3], sA + SW(o));
                }
            }
            {
                uint32_t brow = (uint32_t)(wn*64 + (lsel >> 1)*8 + lrow);
                uint32_t bcol = (uint32_t)(ks*32 + (lsel & 1)*16);
                #pragma unroll
                for (int p = 0; p < 4; ++p){
                    uint32_t o = (brow + p*16)*128 + bcol;
                    LDSM_X4(bb[2*p][0], bb[2*p][1], bb[2*p+1][0], bb[2*p+1][1], sB + SW(o));
                }
            }
            #pragma unroll
            for (int mt = 0; mt < 2; ++mt)
                #pragma unroll
                for (int nt = 0; nt < 8; ++nt)
                    asm volatile(
                      "mma.sync.aligned.m16n8k16.row.col.f32.bf16.bf16.f32 "
                      "{%0,%1,%2,%3}, {%4,%5,%6,%7}, {%8,%9}, {%0,%1,%2,%3};\n"
                      : "+f"(c[mt][nt][0]), "+f"(c[mt][nt][1]),
                        "+f"(c[mt][nt][2]), "+f"(c[mt][nt][3])
                      : "r"(a[mt][0]), "r"(a[mt][1]), "r"(a[mt][2]), "r"(a[mt][3]),
                        "r"(bb[nt][0]), "r"(bb[nt][1]));
        }
    }

    // ---- plane max from accumulator registers ----
    {
        float m = NEG;
        #pragma unroll
        for (int mt = 0; mt < 2; ++mt)
            #pragma unroll
            for (int nt = 0; nt < 8; ++nt){
                float m01 = fmaxf(c[mt][nt][0], c[mt][nt][1]);
                float m23 = fmaxf(c[mt][nt][2], c[mt][nt][3]);
                m = fmaxf(m, fmaxf(m01, m23));
            }
        #pragma unroll
        for (int off = 16; off > 0; off >>= 1)
            m = fmaxf(m, __shfl_xor_sync(0xffffffffu, m, off));
        if (lane == 0) red[warp] = m;
    }
    __syncthreads();
    if (tid == 0){
        float m = red[0];
        #pragma unroll
        for (int w = 1; w < 8; ++w) m = fmaxf(m, red[w]);
        mpp[0] = m;
    }
    __syncthreads();
    const float mp = mpp[0];

    // ---- spill exp(c - mp) into G ----
    #pragma unroll
    for (int mt = 0; mt < 2; ++mt)
        #pragma unroll
        for (int nt = 0; nt < 8; ++nt){
            int row = wm*32 + mt*16 + g;
            int col = wn*64 + nt*8 + tg*2;
            *(float2*)&G[row*GROW + col] =
                make_float2(__expf(c[mt][nt][0]-mp), __expf(c[mt][nt][1]-mp));
            *(float2*)&G[(row+8)*GROW + col] =
                make_float2(__expf(c[mt][nt][2]-mp), __expf(c[mt][nt][3]-mp));
        }
    __syncthreads();

    const int row = tid >> 1, part = tid & 1;

    // ---- row sums ----
    {
        const float* Gr = G + row*GROW + part*64;
        float sum = 0.f;
        #pragma unroll
        for (int q = 0; q < 16; ++q){
            float4 v = *(const float4*)(Gr + q*4);
            sum += (v.x + v.y) + (v.z + v.w);
        }
        sum += __shfl_xor_sync(0xffffffffu, sum, 1);
        if (part == 0){
            rowS[row] = sum;
            int idx = (s*BSZ + aBase + row)*2 + nh;
            g_px2_m[idx] = mp; g_px2_s[idx] = sum;
        }
    }
    __syncthreads();

    // ---- col sums + plane sum ----
    {
        const int col = tid >> 1;
        const float* Gc = G + part*64*GROW + col;
        float sum = 0.f;
        #pragma unroll 8
        for (int rr = 0; rr < 64; ++rr) sum += Gc[rr*GROW];
        sum += __shfl_xor_sync(0xffffffffu, sum, 1);
        if (part == 0){
            int idx = (s*BSZ + rBase + col)*2 + half;
            g_py2_m[idx] = mp; g_py2_s[idx] = sum;
        }
    }
    if (warp < 4){
        float v = rowS[warp*32 + lane];
        #pragma unroll
        for (int off = 16; off > 0; off >>= 1)
            v += __shfl_xor_sync(0xffffffffu, v, off);
        if (lane == 0) red[8 + warp] = v;
    }
    __syncthreads();
    if (tid == 0){
        int idx = s*4 + half*2 + nh;
        g_pz_m[idx] = mp;
        g_pz_s[idx] = (red[8] + red[9]) + (red[10] + red[11]);
    }
}

// ============ finalize: per-line losses + last-block global sum ============
__global__ void finalize(const float* __restrict__ X, const float* __restrict__ Y,
                         const float* __restrict__ Z, float* __restrict__ out){
    __shared__ float wred[8*5];
    __shared__ int lastFlag;
    const int t = blockIdx.x, si = threadIdx.x;
    const int warp = si >> 5, lane = si & 31;

    float Mx = NEG, Sx = 0.f, My = NEG, Sy = 0.f;
    {
        int b = (si*BSZ + t)*2;
        lse_merge(Mx, Sx, g_px2_m[b],   g_px2_s[b]);
        lse_merge(Mx, Sx, g_px2_m[b+1], g_px2_s[b+1]);
        lse_merge(My, Sy, g_py2_m[b],   g_py2_s[b]);
        lse_merge(My, Sy, g_py2_m[b+1], g_py2_s[b+1]);
    }
    float dg = X[t*D + 2*si]   * Y[t*D + 2*si]   * Z[t*D + 2*si]
             + X[t*D + 2*si+1] * Y[t*D + 2*si+1] * Z[t*D + 2*si+1];

    #pragma unroll
    for (int off = 16; off > 0; off >>= 1){
        float m2 = __shfl_xor_sync(0xffffffffu, Mx, off);
        float s2 = __shfl_xor_sync(0xffffffffu, Sx, off);
        lse_merge(Mx, Sx, m2, s2);
        m2 = __shfl_xor_sync(0xffffffffu, My, off);
        s2 = __shfl_xor_sync(0xffffffffu, Sy, off);
        lse_merge(My, Sy, m2, s2);
        dg += __shfl_xor_sync(0xffffffffu, dg, off);
    }
    if (lane == 0){
        wred[warp*5+0] = Mx; wred[warp*5+1] = Sx;
        wred[warp*5+2] = My; wred[warp*5+3] = Sy;
        wred[warp*5+4] = dg;
    }
    __syncthreads();
    if (si == 0){
        float MX = NEG, SX = 0.f, MY = NEG, SY = 0.f, DG = 0.f;
        #pragma unroll
        for (int w = 0; w < 8; ++w){
            lse_merge(MX, SX, wred[w*5+0], wred[w*5+1]);
            lse_merge(MY, SY, wred[w*5+2], wred[w*5+3]);
            DG += wred[w*5+4];
        }
        float MZ = NEG, SZ = 0.f;
        #pragma unroll
        for (int q = 0; q < 4; ++q)
            lse_merge(MZ, SZ, g_pz_m[t*4+q], g_pz_s[t*4+q]);
        g_line[t] = (MX + logf(SX)) + (MY + logf(SY)) + (MZ + logf(SZ)) - 3.f*DG;
        __threadfence();
        lastFlag = (atomicAdd(&g_ctr, 1) == BSZ - 1) ? 1 : 0;
    }
    __syncthreads();
    if (lastFlag){
        if (warp == 0){
            float v = 0.f;
            #pragma unroll
            for (int j = 0; j < 8; ++j) v += g_line[lane + j*32];
            #pragma unroll
            for (int off = 16; off > 0; off >>= 1)
                v += __shfl_xor_sync(0xffffffffu, v, off);
            if (lane == 0){
                out[0] = v / 768.f;
                g_ctr = 0;
            }
        }
    }
}

extern "C" void kernel_launch(void* const* d_in, const int* in_sizes, int n_in,
                              void* d_out, int out_size){
    const float* X = (const float*)d_in[0];
    const float* Y = (const float*)d_in[1];
    const float* Z = (const float*)d_in[2];
    float* out = (float*)d_out;

    cudaFuncSetAttribute(symile_quad, cudaFuncAttributeMaxDynamicSharedMemorySize, SMEM_BYTES);

    conv_kernel<<<192, 256>>>(X, Y, Z);
    symile_quad<<<BSZ*4, 256, SMEM_BYTES>>>();
    finalize<<<BSZ, 256>>>(X, Y, Z, out);
}